// round 3
// baseline (speedup 1.0000x reference)
#include <cuda_runtime.h>
#include <cuda_bf16.h>
#include <math.h>
#include <stdint.h>

#define H 128
#define N_IP_MAX 50000
#define N_CON_MAX 200000

// ---------------- scratch ----------------
__device__ float g_s0[N_IP_MAX * H];
__device__ float g_s1[N_CON_MAX * H];
__device__ float g_s2[N_CON_MAX * H];
__device__ float g_deg0[N_IP_MAX];
__device__ float g_deg1[N_CON_MAX];
__device__ float g_deg2[N_CON_MAX];
__device__ float g_ipA[N_IP_MAX * H];
__device__ float g_ipB[N_IP_MAX * H];
__device__ float g_conA[N_CON_MAX * H];
__device__ float g_conB[N_CON_MAX * H];
__device__ uint2 g_wsplit[10 * 128 * 128];   // per sage: [k-pair 0..127][col 0..127] (hi,lo)

// ---------------- helpers ----------------
__device__ __forceinline__ uint2 split2(float x0, float x1)
{
    uint32_t hi;
    asm("cvt.rn.bf16x2.f32 %0, %1, %2;" : "=r"(hi) : "f"(x1), "f"(x0));
    float h0 = __uint_as_float(hi << 16);
    float h1 = __uint_as_float(hi & 0xffff0000u);
    uint32_t lo;
    asm("cvt.rn.bf16x2.f32 %0, %1, %2;" : "=r"(lo) : "f"(x1 - h1), "f"(x0 - h0));
    return make_uint2(hi, lo);
}

__device__ __forceinline__ void mma16816(float* d, const uint32_t* a, uint32_t b0, uint32_t b1)
{
    asm volatile(
        "mma.sync.aligned.m16n8k16.row.col.f32.bf16.bf16.f32 "
        "{%0,%1,%2,%3}, {%4,%5,%6,%7}, {%8,%9}, {%0,%1,%2,%3};"
        : "+f"(d[0]), "+f"(d[1]), "+f"(d[2]), "+f"(d[3])
        : "r"(a[0]), "r"(a[1]), "r"(a[2]), "r"(a[3]), "r"(b0), "r"(b1));
}

__device__ __forceinline__ void cp_async16(uint32_t smem_dst, const void* gsrc)
{
    asm volatile("cp.async.ca.shared.global [%0], [%1], 16;" :: "r"(smem_dst), "l"(gsrc));
}
__device__ __forceinline__ void cp_commit() { asm volatile("cp.async.commit_group;"); }
__device__ __forceinline__ void cp_wait0()  { asm volatile("cp.async.wait_group 0;" ::: "memory"); }

// ---------------- W pre-split: [Wl;Wr] stacked K=256 -> (hi,lo) k-pairs ----------------
__global__ void presplit_kernel(const float* __restrict__ Wl, const float* __restrict__ Wr,
                                uint2* __restrict__ out)
{
    int idx = blockIdx.x * blockDim.x + threadIdx.x;   // 0..16383
    int p = idx >> 7;          // k-pair 0..127
    int cc = idx & 127;        // col
    int k0 = 2 * p, k1 = 2 * p + 1;
    float x0 = (k0 < H) ? Wl[k0 * H + cc] : Wr[(k0 - H) * H + cc];
    float x1 = (k1 < H) ? Wl[k1 * H + cc] : Wr[(k1 - H) * H + cc];
    out[idx] = split2(x0, x1);
}

// ---------------- scatter-add: one warp per edge, vector red ----------------
__global__ void scatter_kernel(const float* __restrict__ x,
                               const int* __restrict__ src,
                               const int* __restrict__ dst,
                               int nE,
                               float* __restrict__ s,
                               float* __restrict__ deg)
{
    int warp = (blockIdx.x * blockDim.x + threadIdx.x) >> 5;
    int lane = threadIdx.x & 31;
    if (warp >= nE) return;
    int si = src[warp];
    int di = dst[warp];
    float4 v = reinterpret_cast<const float4*>(x)[(size_t)si * (H / 4) + lane];
    float* base = s + (size_t)di * H + lane * 4;
    asm volatile("red.global.add.v4.f32 [%0], {%1,%2,%3,%4};"
                 :: "l"(base), "f"(v.x), "f"(v.y), "f"(v.z), "f"(v.w) : "memory");
    if (lane == 0)
        asm volatile("red.global.add.f32 [%0], %1;" :: "l"(deg + di), "f"(1.0f) : "memory");
}

// ---------------- fused SAGE combine (tensor-core, 3x-bf16 split) ----------------
// A smem: per k-step (16 k), 128 rows x 8 k-pairs, pair order [0,4,1,5,2,6,3,7],
//         each pair stored as uint2(hi,lo). Row stride = 16 u32 (64B). 8KB/buf.
// W smem: 8 pair-rows x 128 cols uint2, pair-row stride 264 u32 (1056B). 8.25KB/buf.
#define ASTRIDE 16
#define WSTRIDE 264

template <bool LRELU>
__global__ void __launch_bounds__(256) combine_mma_kernel(
    const float* __restrict__ s, const float* __restrict__ deg,
    const float* __restrict__ xdst,
    const uint2* __restrict__ wsplit, const float* __restrict__ bb,
    float* __restrict__ out, int n)
{
    __shared__ uint32_t Asm[2][128 * ASTRIDE];
    __shared__ uint32_t Wsm[2][8 * WSTRIDE];
    __shared__ float invd[128];
    __shared__ float ssred[128];

    const int tid  = threadIdx.x;
    const int row0 = blockIdx.x * 128;

    if (tid < 128) {
        int r = row0 + tid;
        invd[tid]  = 1.0f / fmaxf((r < n) ? deg[r] : 1.0f, 1.0f);
        ssred[tid] = 0.0f;
    }

    // ---- producer mapping ----
    const int ar   = tid >> 1;         // A row
    const int half = tid & 1;          // k offset 0/8
    const int grow = row0 + ar;
    const bool rowok = grow < n;

    uint32_t wsm_base[2];
    wsm_base[0] = (uint32_t)__cvta_generic_to_shared(&Wsm[0][0]);
    wsm_base[1] = (uint32_t)__cvta_generic_to_shared(&Wsm[1][0]);

    auto cp_w = [&](int kt, int buf) {
        const uint2* wg = wsplit + kt * 8 * 128;
        int ch0 = tid;          // chunk ids 0..511, 16B each
        int ch1 = tid + 256;
        int p0 = ch0 >> 6, o0 = ch0 & 63;
        int p1 = ch1 >> 6, o1 = ch1 & 63;
        cp_async16(wsm_base[buf] + (p0 * WSTRIDE + o0 * 4) * 4, wg + p0 * 128 + o0 * 2);
        cp_async16(wsm_base[buf] + (p1 * WSTRIDE + o1 * 4) * 4, wg + p1 * 128 + o1 * 2);
        cp_commit();
    };

    float af[8];
    auto load_a = [&](int kt) {
        int k0 = kt * 16 + half * 8;
        const float* ap;
        float sc;
        if (k0 < H) { ap = s    + (size_t)grow * H + k0;       sc = invd[ar]; }
        else        { ap = xdst + (size_t)grow * H + (k0 - H); sc = 1.0f;     }
        float4 f0 = make_float4(0.f, 0.f, 0.f, 0.f), f1 = f0;
        if (rowok) {
            f0 = *reinterpret_cast<const float4*>(ap);
            f1 = *reinterpret_cast<const float4*>(ap + 4);
        }
        af[0] = f0.x * sc; af[1] = f0.y * sc; af[2] = f0.z * sc; af[3] = f0.w * sc;
        af[4] = f1.x * sc; af[5] = f1.y * sc; af[6] = f1.z * sc; af[7] = f1.w * sc;
    };

    auto store_a = [&](int buf) {
#pragma unroll
        for (int j = 0; j < 4; j++) {
            int p = half * 4 + j;                       // pair 0..7
            int q = (p < 4) ? (2 * p) : (2 * (p - 4) + 1);  // permuted slot
            uint2 v = split2(af[2 * j], af[2 * j + 1]);
            *reinterpret_cast<uint2*>(&Asm[buf][ar * ASTRIDE + 2 * q]) = v;
        }
    };

    // ---- mma mapping ----
    const int lane = tid & 31;
    const int wid  = tid >> 5;
    const int wm   = wid >> 2;
    const int wn   = wid & 3;
    const int g    = lane >> 2;
    const int c    = lane & 3;

    float acc[4][4][4];
#pragma unroll
    for (int mt = 0; mt < 4; mt++)
#pragma unroll
        for (int nt = 0; nt < 4; nt++)
#pragma unroll
            for (int j = 0; j < 4; j++) acc[mt][nt][j] = 0.0f;

    // ---- prologue: stage k-step 0 ----
    cp_w(0, 0);
    __syncthreads();        // invd ready before any convert uses it
    load_a(0);
    store_a(0);
    cp_wait0();
    __syncthreads();

    for (int kt = 0; kt < 16; kt++) {
        int b = kt & 1;
        if (kt < 15) {
            cp_w(kt + 1, b ^ 1);
            load_a(kt + 1);
        }

        // frag loads (wide)
        uint32_t ahf[4][4], alf[4][4];
#pragma unroll
        for (int mt = 0; mt < 4; mt++) {
            int R = wm * 64 + mt * 16;
            uint4 v0 = *reinterpret_cast<const uint4*>(&Asm[b][(R + g) * ASTRIDE + c * 4]);
            uint4 v1 = *reinterpret_cast<const uint4*>(&Asm[b][(R + g + 8) * ASTRIDE + c * 4]);
            ahf[mt][0] = v0.x; ahf[mt][1] = v1.x; ahf[mt][2] = v0.z; ahf[mt][3] = v1.z;
            alf[mt][0] = v0.y; alf[mt][1] = v1.y; alf[mt][2] = v0.w; alf[mt][3] = v1.w;
        }
#pragma unroll
        for (int nt = 0; nt < 4; nt++) {
            int col = wn * 32 + nt * 8 + g;
            uint2 w0 = *reinterpret_cast<const uint2*>(&Wsm[b][c * WSTRIDE + col * 2]);
            uint2 w1 = *reinterpret_cast<const uint2*>(&Wsm[b][(c + 4) * WSTRIDE + col * 2]);
#pragma unroll
            for (int mt = 0; mt < 4; mt++) {
                mma16816(acc[mt][nt], ahf[mt], w0.x, w1.x);  // Ah*Bh
                mma16816(acc[mt][nt], ahf[mt], w0.y, w1.y);  // Ah*Bl
                mma16816(acc[mt][nt], alf[mt], w0.x, w1.x);  // Al*Bh
            }
        }

        if (kt < 15) {
            store_a(b ^ 1);
            cp_wait0();
        }
        __syncthreads();
    }

    // ---- epilogue: bias + row L2 norm (+lrelu) ----
#pragma unroll
    for (int mt = 0; mt < 4; mt++) {
        float ss0 = 0.0f, ss1 = 0.0f;
#pragma unroll
        for (int nt = 0; nt < 4; nt++) {
            int col = wn * 32 + nt * 8 + c * 2;
            float b0v = bb[col], b1v = bb[col + 1];
            acc[mt][nt][0] += b0v; acc[mt][nt][1] += b1v;
            acc[mt][nt][2] += b0v; acc[mt][nt][3] += b1v;
            ss0 += acc[mt][nt][0] * acc[mt][nt][0] + acc[mt][nt][1] * acc[mt][nt][1];
            ss1 += acc[mt][nt][2] * acc[mt][nt][2] + acc[mt][nt][3] * acc[mt][nt][3];
        }
        ss0 += __shfl_xor_sync(0xffffffffu, ss0, 1);
        ss0 += __shfl_xor_sync(0xffffffffu, ss0, 2);
        ss1 += __shfl_xor_sync(0xffffffffu, ss1, 1);
        ss1 += __shfl_xor_sync(0xffffffffu, ss1, 2);
        if (c == 0) {
            atomicAdd(&ssred[wm * 64 + mt * 16 + g],     ss0);
            atomicAdd(&ssred[wm * 64 + mt * 16 + 8 + g], ss1);
        }
    }
    __syncthreads();

#pragma unroll
    for (int mt = 0; mt < 4; mt++) {
        int rl0 = wm * 64 + mt * 16 + g;
        int rl1 = rl0 + 8;
        float inv0 = 1.0f / fmaxf(sqrtf(ssred[rl0]), 1e-12f);
        float inv1 = 1.0f / fmaxf(sqrtf(ssred[rl1]), 1e-12f);
        int gr0 = row0 + rl0;
        int gr1 = row0 + rl1;
#pragma unroll
        for (int nt = 0; nt < 4; nt++) {
            int col = wn * 32 + nt * 8 + c * 2;
            if (gr0 < n) {
                float v0 = acc[mt][nt][0] * inv0;
                float v1 = acc[mt][nt][1] * inv0;
                if (LRELU) { v0 = (v0 >= 0.f) ? v0 : 0.01f * v0; v1 = (v1 >= 0.f) ? v1 : 0.01f * v1; }
                *reinterpret_cast<float2*>(out + (size_t)gr0 * H + col) = make_float2(v0, v1);
            }
            if (gr1 < n) {
                float v2 = acc[mt][nt][2] * inv1;
                float v3 = acc[mt][nt][3] * inv1;
                if (LRELU) { v2 = (v2 >= 0.f) ? v2 : 0.01f * v2; v3 = (v3 >= 0.f) ? v3 : 0.01f * v3; }
                *reinterpret_cast<float2*>(out + (size_t)gr1 * H + col) = make_float2(v2, v3);
            }
        }
    }
}

// ---------------- elementwise: out = lrelu(a + b) ----------------
__global__ void sum_lrelu_kernel(const float4* __restrict__ a,
                                 const float4* __restrict__ b,
                                 float4* __restrict__ out, int n4)
{
    int i = blockIdx.x * blockDim.x + threadIdx.x;
    if (i >= n4) return;
    float4 x = a[i], y = b[i];
    float4 r;
    r.x = x.x + y.x; r.x = (r.x >= 0.f) ? r.x : 0.01f * r.x;
    r.y = x.y + y.y; r.y = (r.y >= 0.f) ? r.y : 0.01f * r.y;
    r.z = x.z + y.z; r.z = (r.z >= 0.f) ? r.z : 0.01f * r.z;
    r.w = x.w + y.w; r.w = (r.w >= 0.f) ? r.w : 0.01f * r.w;
    out[i] = r;
}

// ---------------- host ----------------
static inline void run_scatter(const float* x, const int* src, const int* dst, int nE,
                               float* s, float* deg)
{
    int blocks = (nE + 7) / 8;
    scatter_kernel<<<blocks, 256>>>(x, src, dst, nE, s, deg);
}

template <bool LRELU>
static inline void run_combine(const float* s, const float* deg, const float* xdst,
                               const uint2* wsplit, const float* bl,
                               float* out, int n)
{
    int blocks = (n + 127) / 128;
    combine_mma_kernel<LRELU><<<blocks, 256>>>(s, deg, xdst, wsplit, bl, out, n);
}

extern "C" void kernel_launch(void* const* d_in, const int* in_sizes, int n_in,
                              void* d_out, int out_size)
{
    const float* x_ip  = (const float*)d_in[0];
    const float* x_con = (const float*)d_in[1];
    const int* src_ipcon = (const int*)d_in[2];
    const int* dst_ipcon = (const int*)d_in[3];
    const int* src_conip = (const int*)d_in[4];
    const int* dst_conip = (const int*)d_in[5];
    const int* src_ipip  = (const int*)d_in[6];
    const int* dst_ipip  = (const int*)d_in[7];
    const int* src_csrc  = (const int*)d_in[8];
    const int* dst_csrc  = (const int*)d_in[9];
    const int* src_cdst  = (const int*)d_in[10];
    const int* dst_cdst  = (const int*)d_in[11];
    const float* Wl_t = (const float*)d_in[12];
    const float* bl_t = (const float*)d_in[13];
    const float* Wr_t = (const float*)d_in[14];
    const float* Wl_s = (const float*)d_in[15];
    const float* bl_s = (const float*)d_in[16];
    const float* Wr_s = (const float*)d_in[17];

    const int n_ip  = in_sizes[0] / H;
    const int n_con = in_sizes[1] / H;
    const int nE_ipcon = in_sizes[2];
    const int nE_conip = in_sizes[4];
    const int nE_ipip  = in_sizes[6];
    const int nE_csrc  = in_sizes[8];
    const int nE_cdst  = in_sizes[10];

    float *s0, *s1, *s2, *deg0, *deg1, *deg2, *ipA, *ipB, *conA, *conB;
    uint2* wsp;
    cudaGetSymbolAddress((void**)&s0,   g_s0);
    cudaGetSymbolAddress((void**)&s1,   g_s1);
    cudaGetSymbolAddress((void**)&s2,   g_s2);
    cudaGetSymbolAddress((void**)&deg0, g_deg0);
    cudaGetSymbolAddress((void**)&deg1, g_deg1);
    cudaGetSymbolAddress((void**)&deg2, g_deg2);
    cudaGetSymbolAddress((void**)&ipA,  g_ipA);
    cudaGetSymbolAddress((void**)&ipB,  g_ipB);
    cudaGetSymbolAddress((void**)&conA, g_conA);
    cudaGetSymbolAddress((void**)&conB, g_conB);
    cudaGetSymbolAddress((void**)&wsp,  g_wsplit);

    float* out = (float*)d_out;
    const size_t WSZ = 128 * 128;

    // pre-split all 10 weight pairs: temporal l*3+e (0..5), spatial 6 + l*2+e
    for (int l = 0; l < 2; l++) {
        for (int e = 0; e < 3; e++) {
            int sg = l * 3 + e;
            presplit_kernel<<<64, 256>>>(Wl_t + (size_t)sg * H * H,
                                         Wr_t + (size_t)sg * H * H, wsp + (size_t)sg * WSZ);
        }
        for (int e = 0; e < 2; e++) {
            int sg = 6 + l * 2 + e;
            presplit_kernel<<<64, 256>>>(Wl_s + (size_t)(l * 2 + e) * H * H,
                                         Wr_s + (size_t)(l * 2 + e) * H * H, wsp + (size_t)sg * WSZ);
        }
    }

    for (int l = 0; l < 2; l++) {
        const float* xi = (l == 0) ? x_ip  : ipB;
        const float* xc = (l == 0) ? x_con : conB;

        // ---------- temporal ----------
        cudaMemsetAsync(s0,   0, (size_t)n_ip  * H * sizeof(float), 0);
        cudaMemsetAsync(s1,   0, (size_t)n_con * H * sizeof(float), 0);
        cudaMemsetAsync(s2,   0, (size_t)n_con * H * sizeof(float), 0);
        cudaMemsetAsync(deg0, 0, (size_t)n_ip  * sizeof(float), 0);
        cudaMemsetAsync(deg1, 0, (size_t)n_con * sizeof(float), 0);
        cudaMemsetAsync(deg2, 0, (size_t)n_con * sizeof(float), 0);

        run_scatter(xi, src_ipip, dst_ipip, nE_ipip, s0, deg0);
        run_scatter(xc, src_csrc, dst_csrc, nE_csrc, s1, deg1);
        run_scatter(xc, src_cdst, dst_cdst, nE_cdst, s2, deg2);

        const float* b0 = bl_t + (size_t)(l * 3 + 0) * H;
        const float* b1 = bl_t + (size_t)(l * 3 + 1) * H;
        const float* b2 = bl_t + (size_t)(l * 3 + 2) * H;

        run_combine<true >(s0, deg0, xi, wsp + (size_t)(l * 3 + 0) * WSZ, b0, ipA, n_ip);
        run_combine<false>(s1, deg1, xc, wsp + (size_t)(l * 3 + 1) * WSZ, b1, s1,  n_con);
        run_combine<false>(s2, deg2, xc, wsp + (size_t)(l * 3 + 2) * WSZ, b2, s2,  n_con);
        {
            int n4 = n_con * H / 4;
            sum_lrelu_kernel<<<(n4 + 255) / 256, 256>>>(
                (const float4*)s1, (const float4*)s2, (float4*)conA, n4);
        }

        // ---------- spatial ----------
        cudaMemsetAsync(s0,   0, (size_t)n_ip  * H * sizeof(float), 0);
        cudaMemsetAsync(s1,   0, (size_t)n_con * H * sizeof(float), 0);
        cudaMemsetAsync(deg0, 0, (size_t)n_ip  * sizeof(float), 0);
        cudaMemsetAsync(deg1, 0, (size_t)n_con * sizeof(float), 0);

        run_scatter(ipA,  src_ipcon, dst_ipcon, nE_ipcon, s1, deg1);
        run_scatter(conA, src_conip, dst_conip, nE_conip, s0, deg0);

        const float* bs0 = bl_s + (size_t)(l * 2 + 0) * H;
        const float* bs1 = bl_s + (size_t)(l * 2 + 1) * H;

        float* out_ip  = (l == 1) ? out : ipB;
        float* out_con = (l == 1) ? (out + (size_t)n_ip * H) : conB;

        run_combine<true>(s1, deg1, conA, wsp + (size_t)(6 + l * 2 + 0) * WSZ, bs0, out_con, n_con);
        run_combine<true>(s0, deg0, ipA,  wsp + (size_t)(6 + l * 2 + 1) * WSZ, bs1, out_ip,  n_ip);
    }
}

// round 5
// speedup vs baseline: 1.0633x; 1.0633x over previous
#include <cuda_runtime.h>
#include <cuda_bf16.h>
#include <math.h>
#include <stdint.h>

#define H 128
#define N_IP_MAX 50000
#define N_CON_MAX 200000

// ---------------- scratch ----------------
__device__ float g_s0[N_IP_MAX * H];
__device__ float g_s1[N_CON_MAX * H];
__device__ float g_s2[N_CON_MAX * H];
__device__ float g_deg0[N_IP_MAX];
__device__ float g_deg1[N_CON_MAX];
__device__ float g_deg2[N_CON_MAX];
__device__ float g_ipA[N_IP_MAX * H];
__device__ float g_ipB[N_IP_MAX * H];
__device__ float g_conA[N_CON_MAX * H];
__device__ float g_conB[N_CON_MAX * H];
__device__ uint2 g_wsplit[10 * 16384];   // per sage: [k-pair 0..127][col 0..127] (hi,lo)

// ---------------- helpers ----------------
__device__ __forceinline__ uint2 split2(float x0, float x1)
{
    uint32_t hi;
    asm("cvt.rn.bf16x2.f32 %0, %1, %2;" : "=r"(hi) : "f"(x1), "f"(x0));
    float h0 = __uint_as_float(hi << 16);
    float h1 = __uint_as_float(hi & 0xffff0000u);
    uint32_t lo;
    asm("cvt.rn.bf16x2.f32 %0, %1, %2;" : "=r"(lo) : "f"(x1 - h1), "f"(x0 - h0));
    return make_uint2(hi, lo);
}

__device__ __forceinline__ void mma16816(float* d, const uint32_t* a, uint32_t b0, uint32_t b1)
{
    asm volatile(
        "mma.sync.aligned.m16n8k16.row.col.f32.bf16.bf16.f32 "
        "{%0,%1,%2,%3}, {%4,%5,%6,%7}, {%8,%9}, {%0,%1,%2,%3};"
        : "+f"(d[0]), "+f"(d[1]), "+f"(d[2]), "+f"(d[3])
        : "r"(a[0]), "r"(a[1]), "r"(a[2]), "r"(a[3]), "r"(b0), "r"(b1));
}

__device__ __forceinline__ void cp_async16(uint32_t smem_dst, const void* gsrc)
{
    asm volatile("cp.async.ca.shared.global [%0], [%1], 16;" :: "r"(smem_dst), "l"(gsrc));
}
__device__ __forceinline__ void cp_commit() { asm volatile("cp.async.commit_group;"); }
__device__ __forceinline__ void cp_wait0()  { asm volatile("cp.async.wait_group 0;" ::: "memory"); }

// ---------------- W pre-split for all 10 sages (one launch) ----------------
__global__ void presplit_all_kernel(const float* __restrict__ Wl_t, const float* __restrict__ Wr_t,
                                    const float* __restrict__ Wl_s, const float* __restrict__ Wr_s,
                                    uint2* __restrict__ out)
{
    int sg  = blockIdx.y;                                // 0..9
    int idx = blockIdx.x * blockDim.x + threadIdx.x;     // 0..16383
    int p = idx >> 7;           // k-pair
    int col = idx & 127;
    const float *Wl, *Wr;
    if (sg < 6) { Wl = Wl_t + (size_t)sg * H * H;       Wr = Wr_t + (size_t)sg * H * H; }
    else        { Wl = Wl_s + (size_t)(sg - 6) * H * H; Wr = Wr_s + (size_t)(sg - 6) * H * H; }
    int k0 = 2 * p;
    float x0 = (k0 < H)     ? Wl[k0 * H + col]       : Wr[(k0 - H) * H + col];
    float x1 = (k0 + 1 < H) ? Wl[(k0 + 1) * H + col] : Wr[(k0 + 1 - H) * H + col];
    out[(size_t)sg * 16384 + idx] = split2(x0, x1);
}

// ---------------- scatter-add: one warp per edge, vector red ----------------
__global__ void scatter_kernel(const float* __restrict__ x,
                               const int* __restrict__ src,
                               const int* __restrict__ dst,
                               int nE,
                               float* __restrict__ s,
                               float* __restrict__ deg)
{
    int warp = (blockIdx.x * blockDim.x + threadIdx.x) >> 5;
    int lane = threadIdx.x & 31;
    if (warp >= nE) return;
    int si = src[warp];
    int di = dst[warp];
    float4 v = reinterpret_cast<const float4*>(x)[(size_t)si * (H / 4) + lane];
    float* base = s + (size_t)di * H + lane * 4;
    asm volatile("red.global.add.v4.f32 [%0], {%1,%2,%3,%4};"
                 :: "l"(base), "f"(v.x), "f"(v.y), "f"(v.z), "f"(v.w) : "memory");
    if (lane == 0)
        asm volatile("red.global.add.f32 [%0], %1;" :: "l"(deg + di), "f"(1.0f) : "memory");
}

// ---------------- fused SAGE combine (mma.sync, 3x-bf16 split, W fully staged) --------
// CTA: 512 threads (16 warps: 4m x 4n), tile 256 rows x 128 cols, K=256.
// A smem: 2 buffers, [256 rows][8 k-pairs permuted [0,4,1,5,2,6,3,7] as uint2(hi,lo)],
//         row stride ASTRIDE=16 u32. 16KB each.
// W smem: all 128 k-pair rows, [pair][128 cols uint2], pair stride WSTRIDE=264 u32. 132KB.
#define ASTRIDE 16
#define WSTRIDE 264
#define DSMEM_BYTES ((2 * 256 * ASTRIDE + 128 * WSTRIDE) * 4)

template <bool LRELU>
__global__ void __launch_bounds__(512) combine_mma_kernel(
    const float* __restrict__ s, const float* __restrict__ deg,
    const float* __restrict__ xdst,
    const uint2* __restrict__ wsplit, const float* __restrict__ bb,
    float* __restrict__ out, int n)
{
    extern __shared__ uint32_t dyn[];
    uint32_t* Asm0 = dyn;
    uint32_t* Asm1 = dyn + 256 * ASTRIDE;
    uint32_t* Wsm  = dyn + 2 * 256 * ASTRIDE;
    __shared__ float invd[256];
    __shared__ float ssred[256];

    const int tid  = threadIdx.x;
    const int row0 = blockIdx.x * 256;

    // ---- one-shot W stage: 8192 x 16B chunks ----
    {
        uint32_t wb = (uint32_t)__cvta_generic_to_shared(Wsm);
#pragma unroll
        for (int it = 0; it < 16; it++) {
            int ch = tid + it * 512;
            int p = ch >> 6, o = ch & 63;
            cp_async16(wb + (uint32_t)(p * WSTRIDE + o * 4) * 4, wsplit + p * 128 + o * 2);
        }
        cp_commit();
    }

    if (tid < 256) {
        int r = row0 + tid;
        invd[tid]  = 1.0f / fmaxf((r < n) ? deg[r] : 1.0f, 1.0f);
        ssred[tid] = 0.0f;
    }
    __syncthreads();   // invd ready for producers

    // ---- A producer mapping ----
    const int ar   = tid >> 1;       // row 0..255
    const int half = tid & 1;        // k offset 0/8 within k-step
    const int grow = row0 + ar;
    const bool rowok = grow < n;

    float af[8];
    auto load_a = [&](int kt) {
        int k0 = kt * 16 + half * 8;
        const float* ap;
        float sc;
        if (k0 < H) { ap = s    + (size_t)grow * H + k0;       sc = invd[ar]; }
        else        { ap = xdst + (size_t)grow * H + (k0 - H); sc = 1.0f;     }
        float4 f0 = make_float4(0.f, 0.f, 0.f, 0.f), f1 = f0;
        if (rowok) {
            f0 = *reinterpret_cast<const float4*>(ap);
            f1 = *reinterpret_cast<const float4*>(ap + 4);
        }
        af[0] = f0.x * sc; af[1] = f0.y * sc; af[2] = f0.z * sc; af[3] = f0.w * sc;
        af[4] = f1.x * sc; af[5] = f1.y * sc; af[6] = f1.z * sc; af[7] = f1.w * sc;
    };

    auto store_a = [&](uint32_t* buf) {
#pragma unroll
        for (int j = 0; j < 4; j++) {
            int p = half * 4 + j;
            int q = (p < 4) ? (2 * p) : (2 * (p - 4) + 1);
            uint2 v = split2(af[2 * j], af[2 * j + 1]);
            *reinterpret_cast<uint2*>(&buf[ar * ASTRIDE + 2 * q]) = v;
        }
    };

    // ---- mma mapping ----
    const int lane = tid & 31;
    const int wid  = tid >> 5;
    const int wm   = wid >> 2;   // 0..3 (64-row group)
    const int wn   = wid & 3;    // 0..3 (32-col group)
    const int g    = lane >> 2;
    const int c    = lane & 3;

    float acc[4][4][4];
#pragma unroll
    for (int mt = 0; mt < 4; mt++)
#pragma unroll
        for (int nt = 0; nt < 4; nt++)
#pragma unroll
            for (int j = 0; j < 4; j++) acc[mt][nt][j] = 0.0f;

    load_a(0);
    store_a(Asm0);
    cp_wait0();
    __syncthreads();

    for (int kt = 0; kt < 16; kt++) {
        uint32_t* cur = (kt & 1) ? Asm1 : Asm0;
        uint32_t* nxt = (kt & 1) ? Asm0 : Asm1;
        if (kt < 15) load_a(kt + 1);

        uint32_t ahf[4][4], alf[4][4];
#pragma unroll
        for (int mt = 0; mt < 4; mt++) {
            int R = wm * 64 + mt * 16;
            uint4 v0 = *reinterpret_cast<const uint4*>(&cur[(R + g) * ASTRIDE + c * 4]);
            uint4 v1 = *reinterpret_cast<const uint4*>(&cur[(R + g + 8) * ASTRIDE + c * 4]);
            ahf[mt][0] = v0.x; ahf[mt][1] = v1.x; ahf[mt][2] = v0.z; ahf[mt][3] = v1.z;
            alf[mt][0] = v0.y; alf[mt][1] = v1.y; alf[mt][2] = v0.w; alf[mt][3] = v1.w;
        }
#pragma unroll
        for (int nt = 0; nt < 4; nt++) {
            int col = wn * 32 + nt * 8 + g;
            uint2 w0 = *reinterpret_cast<const uint2*>(&Wsm[(kt * 8 + c) * WSTRIDE + col * 2]);
            uint2 w1 = *reinterpret_cast<const uint2*>(&Wsm[(kt * 8 + c + 4) * WSTRIDE + col * 2]);
#pragma unroll
            for (int mt = 0; mt < 4; mt++) {
                mma16816(acc[mt][nt], ahf[mt], w0.x, w1.x);  // Ah*Bh
                mma16816(acc[mt][nt], ahf[mt], w0.y, w1.y);  // Ah*Bl
                mma16816(acc[mt][nt], alf[mt], w0.x, w1.x);  // Al*Bh
            }
        }

        if (kt < 15) store_a(nxt);
        __syncthreads();
    }

    // ---- epilogue: bias + row L2 norm (+lrelu) ----
#pragma unroll
    for (int mt = 0; mt < 4; mt++) {
        float ss0 = 0.0f, ss1 = 0.0f;
#pragma unroll
        for (int nt = 0; nt < 4; nt++) {
            int col = wn * 32 + nt * 8 + c * 2;
            float b0v = __ldg(bb + col), b1v = __ldg(bb + col + 1);
            acc[mt][nt][0] += b0v; acc[mt][nt][1] += b1v;
            acc[mt][nt][2] += b0v; acc[mt][nt][3] += b1v;
            ss0 += acc[mt][nt][0] * acc[mt][nt][0] + acc[mt][nt][1] * acc[mt][nt][1];
            ss1 += acc[mt][nt][2] * acc[mt][nt][2] + acc[mt][nt][3] * acc[mt][nt][3];
        }
        ss0 += __shfl_xor_sync(0xffffffffu, ss0, 1);
        ss0 += __shfl_xor_sync(0xffffffffu, ss0, 2);
        ss1 += __shfl_xor_sync(0xffffffffu, ss1, 1);
        ss1 += __shfl_xor_sync(0xffffffffu, ss1, 2);
        if (c == 0) {
            atomicAdd(&ssred[wm * 64 + mt * 16 + g],     ss0);
            atomicAdd(&ssred[wm * 64 + mt * 16 + 8 + g], ss1);
        }
    }
    __syncthreads();

#pragma unroll
    for (int mt = 0; mt < 4; mt++) {
        int rl0 = wm * 64 + mt * 16 + g;
        int rl1 = rl0 + 8;
        float inv0 = 1.0f / fmaxf(sqrtf(ssred[rl0]), 1e-12f);
        float inv1 = 1.0f / fmaxf(sqrtf(ssred[rl1]), 1e-12f);
        int gr0 = row0 + rl0;
        int gr1 = row0 + rl1;
#pragma unroll
        for (int nt = 0; nt < 4; nt++) {
            int col = wn * 32 + nt * 8 + c * 2;
            if (gr0 < n) {
                float v0 = acc[mt][nt][0] * inv0;
                float v1 = acc[mt][nt][1] * inv0;
                if (LRELU) { v0 = (v0 >= 0.f) ? v0 : 0.01f * v0; v1 = (v1 >= 0.f) ? v1 : 0.01f * v1; }
                *reinterpret_cast<float2*>(out + (size_t)gr0 * H + col) = make_float2(v0, v1);
            }
            if (gr1 < n) {
                float v2 = acc[mt][nt][2] * inv1;
                float v3 = acc[mt][nt][3] * inv1;
                if (LRELU) { v2 = (v2 >= 0.f) ? v2 : 0.01f * v2; v3 = (v3 >= 0.f) ? v3 : 0.01f * v3; }
                *reinterpret_cast<float2*>(out + (size_t)gr1 * H + col) = make_float2(v2, v3);
            }
        }
    }
}

// ---------------- elementwise: out = lrelu(a + b) ----------------
__global__ void sum_lrelu_kernel(const float4* __restrict__ a,
                                 const float4* __restrict__ b,
                                 float4* __restrict__ out, int n4)
{
    int i = blockIdx.x * blockDim.x + threadIdx.x;
    if (i >= n4) return;
    float4 x = a[i], y = b[i];
    float4 r;
    r.x = x.x + y.x; r.x = (r.x >= 0.f) ? r.x : 0.01f * r.x;
    r.y = x.y + y.y; r.y = (r.y >= 0.f) ? r.y : 0.01f * r.y;
    r.z = x.z + y.z; r.z = (r.z >= 0.f) ? r.z : 0.01f * r.z;
    r.w = x.w + y.w; r.w = (r.w >= 0.f) ? r.w : 0.01f * r.w;
    out[i] = r;
}

// ---------------- host ----------------
static inline void run_scatter(const float* x, const int* src, const int* dst, int nE,
                               float* s, float* deg)
{
    int blocks = (nE + 7) / 8;
    scatter_kernel<<<blocks, 256>>>(x, src, dst, nE, s, deg);
}

template <bool LRELU>
static inline void run_combine(const float* s, const float* deg, const float* xdst,
                               const uint2* wsplit, const float* bl,
                               float* out, int n)
{
    int blocks = (n + 255) / 256;
    combine_mma_kernel<LRELU><<<blocks, 512, DSMEM_BYTES>>>(s, deg, xdst, wsplit, bl, out, n);
}

extern "C" void kernel_launch(void* const* d_in, const int* in_sizes, int n_in,
                              void* d_out, int out_size)
{
    const float* x_ip  = (const float*)d_in[0];
    const float* x_con = (const float*)d_in[1];
    const int* src_ipcon = (const int*)d_in[2];
    const int* dst_ipcon = (const int*)d_in[3];
    const int* src_conip = (const int*)d_in[4];
    const int* dst_conip = (const int*)d_in[5];
    const int* src_ipip  = (const int*)d_in[6];
    const int* dst_ipip  = (const int*)d_in[7];
    const int* src_csrc  = (const int*)d_in[8];
    const int* dst_csrc  = (const int*)d_in[9];
    const int* src_cdst  = (const int*)d_in[10];
    const int* dst_cdst  = (const int*)d_in[11];
    const float* Wl_t = (const float*)d_in[12];
    const float* bl_t = (const float*)d_in[13];
    const float* Wr_t = (const float*)d_in[14];
    const float* Wl_s = (const float*)d_in[15];
    const float* bl_s = (const float*)d_in[16];
    const float* Wr_s = (const float*)d_in[17];

    const int n_ip  = in_sizes[0] / H;
    const int n_con = in_sizes[1] / H;
    const int nE_ipcon = in_sizes[2];
    const int nE_conip = in_sizes[4];
    const int nE_ipip  = in_sizes[6];
    const int nE_csrc  = in_sizes[8];
    const int nE_cdst  = in_sizes[10];

    float *s0, *s1, *s2, *deg0, *deg1, *deg2, *ipA, *ipB, *conA, *conB;
    uint2* wsp;
    cudaGetSymbolAddress((void**)&s0,   g_s0);
    cudaGetSymbolAddress((void**)&s1,   g_s1);
    cudaGetSymbolAddress((void**)&s2,   g_s2);
    cudaGetSymbolAddress((void**)&deg0, g_deg0);
    cudaGetSymbolAddress((void**)&deg1, g_deg1);
    cudaGetSymbolAddress((void**)&deg2, g_deg2);
    cudaGetSymbolAddress((void**)&ipA,  g_ipA);
    cudaGetSymbolAddress((void**)&ipB,  g_ipB);
    cudaGetSymbolAddress((void**)&conA, g_conA);
    cudaGetSymbolAddress((void**)&conB, g_conB);
    cudaGetSymbolAddress((void**)&wsp,  g_wsplit);

    cudaFuncSetAttribute(combine_mma_kernel<true>,
                         cudaFuncAttributeMaxDynamicSharedMemorySize, DSMEM_BYTES);
    cudaFuncSetAttribute(combine_mma_kernel<false>,
                         cudaFuncAttributeMaxDynamicSharedMemorySize, DSMEM_BYTES);

    float* out = (float*)d_out;

    presplit_all_kernel<<<dim3(64, 10), 256>>>(Wl_t, Wr_t, Wl_s, Wr_s, wsp);

    for (int l = 0; l < 2; l++) {
        const float* xi = (l == 0) ? x_ip  : ipB;
        const float* xc = (l == 0) ? x_con : conB;

        // ---------- temporal ----------
        cudaMemsetAsync(s0,   0, (size_t)n_ip  * H * sizeof(float), 0);
        cudaMemsetAsync(s1,   0, (size_t)n_con * H * sizeof(float), 0);
        cudaMemsetAsync(s2,   0, (size_t)n_con * H * sizeof(float), 0);
        cudaMemsetAsync(deg0, 0, (size_t)n_ip  * sizeof(float), 0);
        cudaMemsetAsync(deg1, 0, (size_t)n_con * sizeof(float), 0);
        cudaMemsetAsync(deg2, 0, (size_t)n_con * sizeof(float), 0);

        run_scatter(xi, src_ipip, dst_ipip, nE_ipip, s0, deg0);
        run_scatter(xc, src_csrc, dst_csrc, nE_csrc, s1, deg1);
        run_scatter(xc, src_cdst, dst_cdst, nE_cdst, s2, deg2);

        const float* b0 = bl_t + (size_t)(l * 3 + 0) * H;
        const float* b1 = bl_t + (size_t)(l * 3 + 1) * H;
        const float* b2 = bl_t + (size_t)(l * 3 + 2) * H;

        run_combine<true >(s0, deg0, xi, wsp + (size_t)(l * 3 + 0) * 16384, b0, ipA, n_ip);
        run_combine<false>(s1, deg1, xc, wsp + (size_t)(l * 3 + 1) * 16384, b1, s1,  n_con);
        run_combine<false>(s2, deg2, xc, wsp + (size_t)(l * 3 + 2) * 16384, b2, s2,  n_con);
        {
            int n4 = n_con * H / 4;
            sum_lrelu_kernel<<<(n4 + 255) / 256, 256>>>(
                (const float4*)s1, (const float4*)s2, (float4*)conA, n4);
        }

        // ---------- spatial ----------
        cudaMemsetAsync(s0,   0, (size_t)n_ip  * H * sizeof(float), 0);
        cudaMemsetAsync(s1,   0, (size_t)n_con * H * sizeof(float), 0);
        cudaMemsetAsync(deg0, 0, (size_t)n_ip  * sizeof(float), 0);
        cudaMemsetAsync(deg1, 0, (size_t)n_con * sizeof(float), 0);

        run_scatter(ipA,  src_ipcon, dst_ipcon, nE_ipcon, s1, deg1);
        run_scatter(conA, src_conip, dst_conip, nE_conip, s0, deg0);

        const float* bs0 = bl_s + (size_t)(l * 2 + 0) * H;
        const float* bs1 = bl_s + (size_t)(l * 2 + 1) * H;

        float* out_ip  = (l == 1) ? out : ipB;
        float* out_con = (l == 1) ? (out + (size_t)n_ip * H) : conB;

        run_combine<true>(s1, deg1, conA, wsp + (size_t)(6 + l * 2 + 0) * 16384, bs0, out_con, n_con);
        run_combine<true>(s0, deg0, ipA,  wsp + (size_t)(6 + l * 2 + 1) * 16384, bs1, out_ip,  n_ip);
    }
}

// round 6
// speedup vs baseline: 1.3982x; 1.3150x over previous
#include <cuda_runtime.h>
#include <cuda_bf16.h>
#include <math.h>
#include <stdint.h>

#define H 128
#define N_IP_MAX 50000
#define N_CON_MAX 200000
#define MAXB 256   // scan blocks per type (256*1024 >= 200k)

// ---------------- scratch ----------------
__device__ float g_s0[N_IP_MAX * H];
__device__ float g_s1[N_CON_MAX * H];
__device__ float g_s2[N_CON_MAX * H];
__device__ float g_ipA[N_IP_MAX * H];
__device__ float g_ipB[N_IP_MAX * H];
__device__ float g_conA[N_CON_MAX * H];
__device__ float g_conB[N_CON_MAX * H];
__device__ uint2 g_wsplit[10 * 16384];
__device__ int g_cnt[700032];
__device__ int g_off[700064];
__device__ int g_eidx[1800064];
__device__ int g_part[5 * MAXB];

struct EdgeDesc { const int* src; const int* dst; int nE; int n_dst; int dstbase; int ebase; };
struct BuildParams { EdgeDesc e[5]; };

// ---------------- helpers ----------------
__device__ __forceinline__ uint2 split2(float x0, float x1)
{
    uint32_t hi;
    asm("cvt.rn.bf16x2.f32 %0, %1, %2;" : "=r"(hi) : "f"(x1), "f"(x0));
    float h0 = __uint_as_float(hi << 16);
    float h1 = __uint_as_float(hi & 0xffff0000u);
    uint32_t lo;
    asm("cvt.rn.bf16x2.f32 %0, %1, %2;" : "=r"(lo) : "f"(x1 - h1), "f"(x0 - h0));
    return make_uint2(hi, lo);
}

__device__ __forceinline__ void mma16816(float* d, const uint32_t* a, uint32_t b0, uint32_t b1)
{
    asm volatile(
        "mma.sync.aligned.m16n8k16.row.col.f32.bf16.bf16.f32 "
        "{%0,%1,%2,%3}, {%4,%5,%6,%7}, {%8,%9}, {%0,%1,%2,%3};"
        : "+f"(d[0]), "+f"(d[1]), "+f"(d[2]), "+f"(d[3])
        : "r"(a[0]), "r"(a[1]), "r"(a[2]), "r"(a[3]), "r"(b0), "r"(b1));
}

__device__ __forceinline__ void cp_async16(uint32_t smem_dst, const void* gsrc)
{
    asm volatile("cp.async.ca.shared.global [%0], [%1], 16;" :: "r"(smem_dst), "l"(gsrc));
}
__device__ __forceinline__ void cp_commit() { asm volatile("cp.async.commit_group;"); }
__device__ __forceinline__ void cp_wait0()  { asm volatile("cp.async.wait_group 0;" ::: "memory"); }

// ---------------- W pre-split (one launch) ----------------
__global__ void presplit_all_kernel(const float* __restrict__ Wl_t, const float* __restrict__ Wr_t,
                                    const float* __restrict__ Wl_s, const float* __restrict__ Wr_s,
                                    uint2* __restrict__ out)
{
    int sg  = blockIdx.y;
    int idx = blockIdx.x * blockDim.x + threadIdx.x;
    int p = idx >> 7;
    int col = idx & 127;
    const float *Wl, *Wr;
    if (sg < 6) { Wl = Wl_t + (size_t)sg * H * H;       Wr = Wr_t + (size_t)sg * H * H; }
    else        { Wl = Wl_s + (size_t)(sg - 6) * H * H; Wr = Wr_s + (size_t)(sg - 6) * H * H; }
    int k0 = 2 * p;
    float x0 = (k0 < H)     ? Wl[k0 * H + col]       : Wr[(k0 - H) * H + col];
    float x1 = (k0 + 1 < H) ? Wl[(k0 + 1) * H + col] : Wr[(k0 + 1 - H) * H + col];
    out[(size_t)sg * 16384 + idx] = split2(x0, x1);
}

// ---------------- CSR build ----------------
__global__ void count_kernel(BuildParams bp, int* __restrict__ cnt)
{
    int t = blockIdx.y;
    EdgeDesc d = bp.e[t];
    int i = blockIdx.x * blockDim.x + threadIdx.x;
    if (i >= d.nE) return;
    atomicAdd(&cnt[d.dstbase + d.dst[i]], 1);
}

__global__ void scan_phase1(BuildParams bp, const int* __restrict__ cnt,
                            int* __restrict__ off, int* __restrict__ part)
{
    int t = blockIdx.y;
    EdgeDesc d = bp.e[t];
    int L = d.n_dst;
    int i = blockIdx.x * 1024 + threadIdx.x;
    __shared__ int sh[1024];
    int v = (i < L) ? cnt[d.dstbase + i] : 0;
    sh[threadIdx.x] = v;
    __syncthreads();
    for (int o = 1; o < 1024; o <<= 1) {
        int x = (threadIdx.x >= o) ? sh[threadIdx.x - o] : 0;
        __syncthreads();
        sh[threadIdx.x] += x;
        __syncthreads();
    }
    if (i < L) off[d.dstbase + t + i] = sh[threadIdx.x] - v;
    if (threadIdx.x == 1023) part[t * MAXB + blockIdx.x] = sh[1023];
}

__global__ void scan_phase2(int* __restrict__ part)
{
    int t = blockIdx.y;
    __shared__ int sh[MAXB];
    int v = part[t * MAXB + threadIdx.x];
    sh[threadIdx.x] = v;
    __syncthreads();
    for (int o = 1; o < MAXB; o <<= 1) {
        int x = (threadIdx.x >= o) ? sh[threadIdx.x - o] : 0;
        __syncthreads();
        sh[threadIdx.x] += x;
        __syncthreads();
    }
    part[t * MAXB + threadIdx.x] = sh[threadIdx.x] - v;   // exclusive
}

__global__ void scan_phase3(BuildParams bp, int* __restrict__ off, const int* __restrict__ part)
{
    int t = blockIdx.y;
    EdgeDesc d = bp.e[t];
    int L = d.n_dst;
    int i = blockIdx.x * 1024 + threadIdx.x;
    if (i < L) off[d.dstbase + t + i] += part[t * MAXB + blockIdx.x];
    if (i == 0 && blockIdx.x == 0) off[d.dstbase + t + L] = d.nE;
}

__global__ void fill_kernel(BuildParams bp, int* __restrict__ cnt,
                            const int* __restrict__ off, int* __restrict__ eidx)
{
    int t = blockIdx.y;
    EdgeDesc d = bp.e[t];
    int i = blockIdx.x * blockDim.x + threadIdx.x;
    if (i >= d.nE) return;
    int dd = d.dst[i];
    int pos = off[d.dstbase + t + dd] + atomicAdd(&cnt[d.dstbase + dd], 1);
    eidx[d.ebase + pos] = d.src[i];
}

// ---------------- CSR mean-aggregation: one warp per dst row ----------------
__global__ void agg_kernel(const float* __restrict__ x, const int* __restrict__ off,
                           const int* __restrict__ eidx, float* __restrict__ s, int n_dst)
{
    int w = (blockIdx.x * blockDim.x + threadIdx.x) >> 5;
    int lane = threadIdx.x & 31;
    if (w >= n_dst) return;
    int start = off[w], end = off[w + 1];
    float4 acc = make_float4(0.f, 0.f, 0.f, 0.f);
    for (int e = start; e < end; e++) {
        int si = __ldg(eidx + e);
        float4 v = reinterpret_cast<const float4*>(x)[(size_t)si * 32 + lane];
        acc.x += v.x; acc.y += v.y; acc.z += v.z; acc.w += v.w;
    }
    float inv = 1.0f / (float)max(end - start, 1);
    acc.x *= inv; acc.y *= inv; acc.z *= inv; acc.w *= inv;
    reinterpret_cast<float4*>(s)[(size_t)w * 32 + lane] = acc;
}

// ---------------- fused SAGE combine (mma.sync, 3x-bf16 split, W fully staged) --------
// MODE: 0 = norm only; 1 = norm+lrelu; 2 = norm + addin + lrelu
#define ASTRIDE 16
#define WSTRIDE 264
#define DSMEM_BYTES ((2 * 256 * ASTRIDE + 128 * WSTRIDE) * 4)

template <int MODE>
__global__ void __launch_bounds__(512) combine_mma_kernel(
    const float* __restrict__ s, const float* __restrict__ xdst,
    const uint2* __restrict__ wsplit, const float* __restrict__ bb,
    const float* __restrict__ addin, float* __restrict__ out, int n)
{
    extern __shared__ uint32_t dyn[];
    uint32_t* Asm0 = dyn;
    uint32_t* Asm1 = dyn + 256 * ASTRIDE;
    uint32_t* Wsm  = dyn + 2 * 256 * ASTRIDE;
    __shared__ float ssred[256];

    const int tid  = threadIdx.x;
    const int row0 = blockIdx.x * 256;

    // one-shot W stage
    {
        uint32_t wb = (uint32_t)__cvta_generic_to_shared(Wsm);
#pragma unroll
        for (int it = 0; it < 16; it++) {
            int ch = tid + it * 512;
            int p = ch >> 6, o = ch & 63;
            cp_async16(wb + (uint32_t)(p * WSTRIDE + o * 4) * 4, wsplit + p * 128 + o * 2);
        }
        cp_commit();
    }
    if (tid < 256) ssred[tid] = 0.0f;

    // ---- A producer mapping ----
    const int ar   = tid >> 1;
    const int half = tid & 1;
    const int grow = row0 + ar;
    const bool rowok = grow < n;

    float af[8];
    auto load_a = [&](int kt) {
        int k0 = kt * 16 + half * 8;
        const float* ap = (k0 < H) ? (s + (size_t)grow * H + k0)
                                   : (xdst + (size_t)grow * H + (k0 - H));
        float4 f0 = make_float4(0.f, 0.f, 0.f, 0.f), f1 = f0;
        if (rowok) {
            f0 = *reinterpret_cast<const float4*>(ap);
            f1 = *reinterpret_cast<const float4*>(ap + 4);
        }
        af[0] = f0.x; af[1] = f0.y; af[2] = f0.z; af[3] = f0.w;
        af[4] = f1.x; af[5] = f1.y; af[6] = f1.z; af[7] = f1.w;
    };

    auto store_a = [&](uint32_t* buf) {
#pragma unroll
        for (int j = 0; j < 4; j++) {
            int p = half * 4 + j;
            int q = (p < 4) ? (2 * p) : (2 * (p - 4) + 1);
            uint2 v = split2(af[2 * j], af[2 * j + 1]);
            *reinterpret_cast<uint2*>(&buf[ar * ASTRIDE + 2 * q]) = v;
        }
    };

    // ---- mma mapping ----
    const int lane = tid & 31;
    const int wid  = tid >> 5;
    const int wm   = wid >> 2;
    const int wn   = wid & 3;
    const int g    = lane >> 2;
    const int c    = lane & 3;

    float acc[4][4][4];
#pragma unroll
    for (int mt = 0; mt < 4; mt++)
#pragma unroll
        for (int nt = 0; nt < 4; nt++)
#pragma unroll
            for (int j = 0; j < 4; j++) acc[mt][nt][j] = 0.0f;

    load_a(0);
    store_a(Asm0);
    cp_wait0();
    __syncthreads();

    for (int kt = 0; kt < 16; kt++) {
        uint32_t* cur = (kt & 1) ? Asm1 : Asm0;
        uint32_t* nxt = (kt & 1) ? Asm0 : Asm1;
        if (kt < 15) load_a(kt + 1);

        uint32_t ahf[4][4], alf[4][4];
#pragma unroll
        for (int mt = 0; mt < 4; mt++) {
            int R = wm * 64 + mt * 16;
            uint4 v0 = *reinterpret_cast<const uint4*>(&cur[(R + g) * ASTRIDE + c * 4]);
            uint4 v1 = *reinterpret_cast<const uint4*>(&cur[(R + g + 8) * ASTRIDE + c * 4]);
            ahf[mt][0] = v0.x; ahf[mt][1] = v1.x; ahf[mt][2] = v0.z; ahf[mt][3] = v1.z;
            alf[mt][0] = v0.y; alf[mt][1] = v1.y; alf[mt][2] = v0.w; alf[mt][3] = v1.w;
        }
#pragma unroll
        for (int nt = 0; nt < 4; nt++) {
            int col = wn * 32 + nt * 8 + g;
            uint2 w0 = *reinterpret_cast<const uint2*>(&Wsm[(kt * 8 + c) * WSTRIDE + col * 2]);
            uint2 w1 = *reinterpret_cast<const uint2*>(&Wsm[(kt * 8 + c + 4) * WSTRIDE + col * 2]);
#pragma unroll
            for (int mt = 0; mt < 4; mt++) {
                mma16816(acc[mt][nt], ahf[mt], w0.x, w1.x);
                mma16816(acc[mt][nt], ahf[mt], w0.y, w1.y);
                mma16816(acc[mt][nt], alf[mt], w0.x, w1.x);
            }
        }

        if (kt < 15) store_a(nxt);
        __syncthreads();
    }

    // ---- epilogue ----
#pragma unroll
    for (int mt = 0; mt < 4; mt++) {
        float ss0 = 0.0f, ss1 = 0.0f;
#pragma unroll
        for (int nt = 0; nt < 4; nt++) {
            int col = wn * 32 + nt * 8 + c * 2;
            float b0v = __ldg(bb + col), b1v = __ldg(bb + col + 1);
            acc[mt][nt][0] += b0v; acc[mt][nt][1] += b1v;
            acc[mt][nt][2] += b0v; acc[mt][nt][3] += b1v;
            ss0 += acc[mt][nt][0] * acc[mt][nt][0] + acc[mt][nt][1] * acc[mt][nt][1];
            ss1 += acc[mt][nt][2] * acc[mt][nt][2] + acc[mt][nt][3] * acc[mt][nt][3];
        }
        ss0 += __shfl_xor_sync(0xffffffffu, ss0, 1);
        ss0 += __shfl_xor_sync(0xffffffffu, ss0, 2);
        ss1 += __shfl_xor_sync(0xffffffffu, ss1, 1);
        ss1 += __shfl_xor_sync(0xffffffffu, ss1, 2);
        if (c == 0) {
            atomicAdd(&ssred[wm * 64 + mt * 16 + g],     ss0);
            atomicAdd(&ssred[wm * 64 + mt * 16 + 8 + g], ss1);
        }
    }
    __syncthreads();

#pragma unroll
    for (int mt = 0; mt < 4; mt++) {
        int rl0 = wm * 64 + mt * 16 + g;
        int rl1 = rl0 + 8;
        float inv0 = 1.0f / fmaxf(sqrtf(ssred[rl0]), 1e-12f);
        float inv1 = 1.0f / fmaxf(sqrtf(ssred[rl1]), 1e-12f);
        int gr0 = row0 + rl0;
        int gr1 = row0 + rl1;
#pragma unroll
        for (int nt = 0; nt < 4; nt++) {
            int col = wn * 32 + nt * 8 + c * 2;
            if (gr0 < n) {
                float v0 = acc[mt][nt][0] * inv0;
                float v1 = acc[mt][nt][1] * inv0;
                if (MODE == 2) {
                    float2 a2 = *reinterpret_cast<const float2*>(addin + (size_t)gr0 * H + col);
                    v0 += a2.x; v1 += a2.y;
                }
                if (MODE >= 1) {
                    v0 = (v0 >= 0.f) ? v0 : 0.01f * v0;
                    v1 = (v1 >= 0.f) ? v1 : 0.01f * v1;
                }
                *reinterpret_cast<float2*>(out + (size_t)gr0 * H + col) = make_float2(v0, v1);
            }
            if (gr1 < n) {
                float v2 = acc[mt][nt][2] * inv1;
                float v3 = acc[mt][nt][3] * inv1;
                if (MODE == 2) {
                    float2 a2 = *reinterpret_cast<const float2*>(addin + (size_t)gr1 * H + col);
                    v2 += a2.x; v3 += a2.y;
                }
                if (MODE >= 1) {
                    v2 = (v2 >= 0.f) ? v2 : 0.01f * v2;
                    v3 = (v3 >= 0.f) ? v3 : 0.01f * v3;
                }
                *reinterpret_cast<float2*>(out + (size_t)gr1 * H + col) = make_float2(v2, v3);
            }
        }
    }
}

// ---------------- host ----------------
static inline void run_agg(const float* x, const int* off, const int* eidx, float* s, int n_dst)
{
    int blocks = (n_dst * 32 + 255) / 256;
    agg_kernel<<<blocks, 256>>>(x, off, eidx, s, n_dst);
}

template <int MODE>
static inline void run_combine(const float* s, const float* xdst,
                               const uint2* wsplit, const float* bl,
                               const float* addin, float* out, int n)
{
    int blocks = (n + 255) / 256;
    combine_mma_kernel<MODE><<<blocks, 512, DSMEM_BYTES>>>(s, xdst, wsplit, bl, addin, out, n);
}

extern "C" void kernel_launch(void* const* d_in, const int* in_sizes, int n_in,
                              void* d_out, int out_size)
{
    const float* x_ip  = (const float*)d_in[0];
    const float* x_con = (const float*)d_in[1];
    const int* src_ipcon = (const int*)d_in[2];
    const int* dst_ipcon = (const int*)d_in[3];
    const int* src_conip = (const int*)d_in[4];
    const int* dst_conip = (const int*)d_in[5];
    const int* src_ipip  = (const int*)d_in[6];
    const int* dst_ipip  = (const int*)d_in[7];
    const int* src_csrc  = (const int*)d_in[8];
    const int* dst_csrc  = (const int*)d_in[9];
    const int* src_cdst  = (const int*)d_in[10];
    const int* dst_cdst  = (const int*)d_in[11];
    const float* Wl_t = (const float*)d_in[12];
    const float* bl_t = (const float*)d_in[13];
    const float* Wr_t = (const float*)d_in[14];
    const float* Wl_s = (const float*)d_in[15];
    const float* bl_s = (const float*)d_in[16];
    const float* Wr_s = (const float*)d_in[17];

    const int n_ip  = in_sizes[0] / H;
    const int n_con = in_sizes[1] / H;
    const int nE_ipcon = in_sizes[2];
    const int nE_conip = in_sizes[4];
    const int nE_ipip  = in_sizes[6];
    const int nE_csrc  = in_sizes[8];
    const int nE_cdst  = in_sizes[10];

    float *s0, *s1, *s2, *ipA, *ipB, *conA, *conB;
    uint2* wsp;
    int *cnt, *off, *eidx, *part;
    cudaGetSymbolAddress((void**)&s0,   g_s0);
    cudaGetSymbolAddress((void**)&s1,   g_s1);
    cudaGetSymbolAddress((void**)&s2,   g_s2);
    cudaGetSymbolAddress((void**)&ipA,  g_ipA);
    cudaGetSymbolAddress((void**)&ipB,  g_ipB);
    cudaGetSymbolAddress((void**)&conA, g_conA);
    cudaGetSymbolAddress((void**)&conB, g_conB);
    cudaGetSymbolAddress((void**)&wsp,  g_wsplit);
    cudaGetSymbolAddress((void**)&cnt,  g_cnt);
    cudaGetSymbolAddress((void**)&off,  g_off);
    cudaGetSymbolAddress((void**)&eidx, g_eidx);
    cudaGetSymbolAddress((void**)&part, g_part);

    cudaFuncSetAttribute(combine_mma_kernel<0>, cudaFuncAttributeMaxDynamicSharedMemorySize, DSMEM_BYTES);
    cudaFuncSetAttribute(combine_mma_kernel<1>, cudaFuncAttributeMaxDynamicSharedMemorySize, DSMEM_BYTES);
    cudaFuncSetAttribute(combine_mma_kernel<2>, cudaFuncAttributeMaxDynamicSharedMemorySize, DSMEM_BYTES);

    float* out = (float*)d_out;

    // ---- CSR build params (types: 0 ipip, 1 csrc, 2 cdst, 3 ipcon, 4 conip) ----
    BuildParams bp;
    bp.e[0] = { src_ipip,  dst_ipip,  nE_ipip,  n_ip,  0,                    0 };
    bp.e[1] = { src_csrc,  dst_csrc,  nE_csrc,  n_con, n_ip,                 nE_ipip };
    bp.e[2] = { src_cdst,  dst_cdst,  nE_cdst,  n_con, n_ip + n_con,         nE_ipip + nE_csrc };
    bp.e[3] = { src_ipcon, dst_ipcon, nE_ipcon, n_con, n_ip + 2 * n_con,     nE_ipip + nE_csrc + nE_cdst };
    bp.e[4] = { src_conip, dst_conip, nE_conip, n_ip,  n_ip + 3 * n_con,     nE_ipip + nE_csrc + nE_cdst + nE_ipcon };
    const int totdst = n_ip * 2 + n_con * 3;

    int maxE = nE_ipip;
    if (nE_csrc  > maxE) maxE = nE_csrc;
    if (nE_cdst  > maxE) maxE = nE_cdst;
    if (nE_ipcon > maxE) maxE = nE_ipcon;
    if (nE_conip > maxE) maxE = nE_conip;

    presplit_all_kernel<<<dim3(64, 10), 256>>>(Wl_t, Wr_t, Wl_s, Wr_s, wsp);

    cudaMemsetAsync(cnt, 0, (size_t)totdst * sizeof(int), 0);
    count_kernel<<<dim3((maxE + 255) / 256, 5), 256>>>(bp, cnt);
    scan_phase1<<<dim3(MAXB, 5), 1024>>>(bp, cnt, off, part);
    scan_phase2<<<dim3(1, 5), MAXB>>>(part);
    scan_phase3<<<dim3(MAXB, 5), 1024>>>(bp, off, part);
    cudaMemsetAsync(cnt, 0, (size_t)totdst * sizeof(int), 0);
    fill_kernel<<<dim3((maxE + 255) / 256, 5), 256>>>(bp, cnt, off, eidx);

    const int* off0 = off + bp.e[0].dstbase + 0;
    const int* off1 = off + bp.e[1].dstbase + 1;
    const int* off2 = off + bp.e[2].dstbase + 2;
    const int* off3 = off + bp.e[3].dstbase + 3;
    const int* off4 = off + bp.e[4].dstbase + 4;
    const int* ei0 = eidx + bp.e[0].ebase;
    const int* ei1 = eidx + bp.e[1].ebase;
    const int* ei2 = eidx + bp.e[2].ebase;
    const int* ei3 = eidx + bp.e[3].ebase;
    const int* ei4 = eidx + bp.e[4].ebase;

    for (int l = 0; l < 2; l++) {
        const float* xi = (l == 0) ? x_ip  : ipB;
        const float* xc = (l == 0) ? x_con : conB;

        // ---------- temporal ----------
        run_agg(xi, off0, ei0, s0, n_ip);
        run_agg(xc, off1, ei1, s1, n_con);
        run_agg(xc, off2, ei2, s2, n_con);

        const float* b0 = bl_t + (size_t)(l * 3 + 0) * H;
        const float* b1 = bl_t + (size_t)(l * 3 + 1) * H;
        const float* b2 = bl_t + (size_t)(l * 3 + 2) * H;

        run_combine<1>(s0, xi, wsp + (size_t)(l * 3 + 0) * 16384, b0, nullptr, ipA, n_ip);
        run_combine<0>(s1, xc, wsp + (size_t)(l * 3 + 1) * 16384, b1, nullptr, s1,  n_con);
        run_combine<2>(s2, xc, wsp + (size_t)(l * 3 + 2) * 16384, b2, s1, conA, n_con);

        // ---------- spatial ----------
        run_agg(ipA,  off3, ei3, s1, n_con);   // ip -> con
        run_agg(conA, off4, ei4, s0, n_ip);    // con -> ip

        const float* bs0 = bl_s + (size_t)(l * 2 + 0) * H;
        const float* bs1 = bl_s + (size_t)(l * 2 + 1) * H;

        float* out_ip  = (l == 1) ? out : ipB;
        float* out_con = (l == 1) ? (out + (size_t)n_ip * H) : conB;

        run_combine<1>(s1, conA, wsp + (size_t)(6 + l * 2 + 0) * 16384, bs0, nullptr, out_con, n_con);
        run_combine<1>(s0, ipA,  wsp + (size_t)(6 + l * 2 + 1) * 16384, bs1, nullptr, out_ip,  n_ip);
    }
}

// round 7
// speedup vs baseline: 1.4548x; 1.0405x over previous
#include <cuda_runtime.h>
#include <cuda_bf16.h>
#include <math.h>
#include <stdint.h>

#define H 128
#define N_IP_MAX 50000
#define N_CON_MAX 200000
#define MAXB 256

// ---------------- scratch ----------------
__device__ float g_s0[N_IP_MAX * H];
__device__ float g_s1[N_CON_MAX * H];
__device__ float g_s2[N_CON_MAX * H];
__device__ float g_ipA[N_IP_MAX * H];
__device__ float g_ipB[N_IP_MAX * H];
__device__ float g_conA[N_CON_MAX * H];
__device__ float g_conB[N_CON_MAX * H];
__device__ uint2 g_wsplit[10 * 16384];
__device__ int g_cnt[700032];      // .bss zero; fill counts it back down to zero
__device__ int g_off[700064];
__device__ int g_eidx[1800064];
__device__ int g_part[5 * MAXB];

struct EdgeDesc { const int* src; const int* dst; int nE; int n_dst; int dstbase; int ebase; };
struct BuildParams { EdgeDesc e[5]; };
struct AggSeg { const float* x; const int* off; const int* eidx; float* s; int n; };
struct CombSeg {
    const float* s; const float* xdst; const uint2* w; const float* bb;
    const float* addin; float* out; int n; int nblk; int mode;  // 0 norm,1 +lrelu,2 +addin+lrelu
};

// ---------------- helpers ----------------
__device__ __forceinline__ uint2 split2(float x0, float x1)
{
    uint32_t hi;
    asm("cvt.rn.bf16x2.f32 %0, %1, %2;" : "=r"(hi) : "f"(x1), "f"(x0));
    float h0 = __uint_as_float(hi << 16);
    float h1 = __uint_as_float(hi & 0xffff0000u);
    uint32_t lo;
    asm("cvt.rn.bf16x2.f32 %0, %1, %2;" : "=r"(lo) : "f"(x1 - h1), "f"(x0 - h0));
    return make_uint2(hi, lo);
}

__device__ __forceinline__ void mma16816(float* d, const uint32_t* a, uint32_t b0, uint32_t b1)
{
    asm volatile(
        "mma.sync.aligned.m16n8k16.row.col.f32.bf16.bf16.f32 "
        "{%0,%1,%2,%3}, {%4,%5,%6,%7}, {%8,%9}, {%0,%1,%2,%3};"
        : "+f"(d[0]), "+f"(d[1]), "+f"(d[2]), "+f"(d[3])
        : "r"(a[0]), "r"(a[1]), "r"(a[2]), "r"(a[3]), "r"(b0), "r"(b1));
}

__device__ __forceinline__ void cp_async16(uint32_t smem_dst, const void* gsrc)
{
    asm volatile("cp.async.ca.shared.global [%0], [%1], 16;" :: "r"(smem_dst), "l"(gsrc));
}
__device__ __forceinline__ void cp_commit() { asm volatile("cp.async.commit_group;"); }
__device__ __forceinline__ void cp_wait0()  { asm volatile("cp.async.wait_group 0;" ::: "memory"); }

// ---------------- fused presplit + degree count ----------------
__global__ void precount_kernel(const float* __restrict__ Wl_t, const float* __restrict__ Wr_t,
                                const float* __restrict__ Wl_s, const float* __restrict__ Wr_s,
                                uint2* __restrict__ out, BuildParams bp,
                                int* __restrict__ cnt, int cntBlocks)
{
    int bx = blockIdx.x;
    if (bx < 640) {
        int sg  = bx >> 6;
        int idx = (bx & 63) * 256 + threadIdx.x;
        int p = idx >> 7;
        int col = idx & 127;
        const float *Wl, *Wr;
        if (sg < 6) { Wl = Wl_t + (size_t)sg * H * H;       Wr = Wr_t + (size_t)sg * H * H; }
        else        { Wl = Wl_s + (size_t)(sg - 6) * H * H; Wr = Wr_s + (size_t)(sg - 6) * H * H; }
        int k0 = 2 * p;
        float x0 = (k0 < H)     ? Wl[k0 * H + col]       : Wr[(k0 - H) * H + col];
        float x1 = (k0 + 1 < H) ? Wl[(k0 + 1) * H + col] : Wr[(k0 + 1 - H) * H + col];
        out[(size_t)sg * 16384 + idx] = split2(x0, x1);
    } else {
        int b2 = bx - 640;
        int t = b2 / cntBlocks;
        int i = (b2 % cntBlocks) * 256 + threadIdx.x;
        EdgeDesc d = bp.e[t];
        if (i < d.nE) atomicAdd(&cnt[d.dstbase + d.dst[i]], 1);
    }
}

// ---------------- CSR scans ----------------
__global__ void scan_phase1(BuildParams bp, const int* __restrict__ cnt,
                            int* __restrict__ off, int* __restrict__ part)
{
    int t = blockIdx.y;
    EdgeDesc d = bp.e[t];
    int L = d.n_dst;
    int i = blockIdx.x * 1024 + threadIdx.x;
    __shared__ int sh[1024];
    int v = (i < L) ? cnt[d.dstbase + i] : 0;
    sh[threadIdx.x] = v;
    __syncthreads();
    for (int o = 1; o < 1024; o <<= 1) {
        int x = (threadIdx.x >= o) ? sh[threadIdx.x - o] : 0;
        __syncthreads();
        sh[threadIdx.x] += x;
        __syncthreads();
    }
    if (i < L) off[d.dstbase + t + i] = sh[threadIdx.x] - v;
    if (threadIdx.x == 1023) part[t * MAXB + blockIdx.x] = sh[1023];
}

__global__ void scan_phase23(BuildParams bp, int* __restrict__ off, const int* __restrict__ part)
{
    int t = blockIdx.y;
    EdgeDesc d = bp.e[t];
    int L = d.n_dst;
    __shared__ int pref[MAXB];
    if (threadIdx.x < MAXB) pref[threadIdx.x] = part[t * MAXB + threadIdx.x];
    __syncthreads();
    // inclusive scan over MAXB entries (first MAXB threads)
    for (int o = 1; o < MAXB; o <<= 1) {
        int x = 0;
        if (threadIdx.x < MAXB && threadIdx.x >= o) x = pref[threadIdx.x - o];
        __syncthreads();
        if (threadIdx.x < MAXB) pref[threadIdx.x] += x;
        __syncthreads();
    }
    int add = (blockIdx.x == 0) ? 0 : pref[blockIdx.x - 1];
    int i = blockIdx.x * 1024 + threadIdx.x;
    if (i < L) off[d.dstbase + t + i] += add;
    if (blockIdx.x == 0 && threadIdx.x == 0) off[d.dstbase + t + L] = d.nE;
}

// fill: counts cnt back DOWN to zero (self-reinitializing across calls/replays)
__global__ void fill_kernel(BuildParams bp, int* __restrict__ cnt,
                            const int* __restrict__ off, int* __restrict__ eidx)
{
    int t = blockIdx.y;
    EdgeDesc d = bp.e[t];
    int i = blockIdx.x * blockDim.x + threadIdx.x;
    if (i >= d.nE) return;
    int dd = d.dst[i];
    int pos = off[d.dstbase + t + dd] + atomicAdd(&cnt[d.dstbase + dd], -1) - 1;
    eidx[d.ebase + pos] = d.src[i];
}

// ---------------- fused CSR mean-aggregation (up to 3 segments) ----------------
__global__ void agg_fused_kernel(AggSeg a0, AggSeg a1, AggSeg a2)
{
    AggSeg sg;
    if (blockIdx.y == 0) sg = a0;
    else if (blockIdx.y == 1) sg = a1;
    else sg = a2;
    int w = (blockIdx.x * blockDim.x + threadIdx.x) >> 5;
    int lane = threadIdx.x & 31;
    if (w >= sg.n) return;
    int start = sg.off[w], end = sg.off[w + 1];
    float4 acc = make_float4(0.f, 0.f, 0.f, 0.f);
    for (int e = start; e < end; e++) {
        int si = __ldg(sg.eidx + e);
        float4 v = reinterpret_cast<const float4*>(sg.x)[(size_t)si * 32 + lane];
        acc.x += v.x; acc.y += v.y; acc.z += v.z; acc.w += v.w;
    }
    float inv = 1.0f / (float)max(end - start, 1);
    acc.x *= inv; acc.y *= inv; acc.z *= inv; acc.w *= inv;
    reinterpret_cast<float4*>(sg.s)[(size_t)w * 32 + lane] = acc;
}

// ---------------- fused SAGE combine (mma.sync, 3x-bf16 split, 2 segments) --------
#define ASTRIDE 16
#define WSTRIDE 264
#define DSMEM_BYTES ((2 * 256 * ASTRIDE + 128 * WSTRIDE) * 4)

__global__ void __launch_bounds__(512) combine_fused_kernel(CombSeg A, CombSeg B)
{
    extern __shared__ uint32_t dyn[];
    uint32_t* Asm0 = dyn;
    uint32_t* Asm1 = dyn + 256 * ASTRIDE;
    uint32_t* Wsm  = dyn + 2 * 256 * ASTRIDE;
    __shared__ float ssred[256];

    CombSeg cs;
    int blk = blockIdx.x;
    if (blk < A.nblk) cs = A;
    else { blk -= A.nblk; cs = B; }

    const int tid  = threadIdx.x;
    const int row0 = blk * 256;
    const int n    = cs.n;
    const int mode = cs.mode;

    // one-shot W stage
    {
        uint32_t wb = (uint32_t)__cvta_generic_to_shared(Wsm);
#pragma unroll
        for (int it = 0; it < 16; it++) {
            int ch = tid + it * 512;
            int p = ch >> 6, o = ch & 63;
            cp_async16(wb + (uint32_t)(p * WSTRIDE + o * 4) * 4, cs.w + p * 128 + o * 2);
        }
        cp_commit();
    }
    if (tid < 256) ssred[tid] = 0.0f;

    // ---- A producer mapping ----
    const int ar   = tid >> 1;
    const int half = tid & 1;
    const int grow = row0 + ar;
    const bool rowok = grow < n;

    float af[8];
    auto load_a = [&](int kt) {
        int k0 = kt * 16 + half * 8;
        const float* ap = (k0 < H) ? (cs.s + (size_t)grow * H + k0)
                                   : (cs.xdst + (size_t)grow * H + (k0 - H));
        float4 f0 = make_float4(0.f, 0.f, 0.f, 0.f), f1 = f0;
        if (rowok) {
            f0 = *reinterpret_cast<const float4*>(ap);
            f1 = *reinterpret_cast<const float4*>(ap + 4);
        }
        af[0] = f0.x; af[1] = f0.y; af[2] = f0.z; af[3] = f0.w;
        af[4] = f1.x; af[5] = f1.y; af[6] = f1.z; af[7] = f1.w;
    };

    auto store_a = [&](uint32_t* buf) {
#pragma unroll
        for (int j = 0; j < 4; j++) {
            int p = half * 4 + j;
            int q = (p < 4) ? (2 * p) : (2 * (p - 4) + 1);
            uint2 v = split2(af[2 * j], af[2 * j + 1]);
            *reinterpret_cast<uint2*>(&buf[ar * ASTRIDE + 2 * q]) = v;
        }
    };

    // ---- mma mapping ----
    const int lane = tid & 31;
    const int wid  = tid >> 5;
    const int wm   = wid >> 2;
    const int wn   = wid & 3;
    const int g    = lane >> 2;
    const int c    = lane & 3;

    float acc[4][4][4];
#pragma unroll
    for (int mt = 0; mt < 4; mt++)
#pragma unroll
        for (int nt = 0; nt < 4; nt++)
#pragma unroll
            for (int j = 0; j < 4; j++) acc[mt][nt][j] = 0.0f;

    load_a(0);
    store_a(Asm0);
    cp_wait0();
    __syncthreads();

    for (int kt = 0; kt < 16; kt++) {
        uint32_t* cur = (kt & 1) ? Asm1 : Asm0;
        uint32_t* nxt = (kt & 1) ? Asm0 : Asm1;
        if (kt < 15) load_a(kt + 1);

        uint32_t ahf[4][4], alf[4][4];
#pragma unroll
        for (int mt = 0; mt < 4; mt++) {
            int R = wm * 64 + mt * 16;
            uint4 v0 = *reinterpret_cast<const uint4*>(&cur[(R + g) * ASTRIDE + c * 4]);
            uint4 v1 = *reinterpret_cast<const uint4*>(&cur[(R + g + 8) * ASTRIDE + c * 4]);
            ahf[mt][0] = v0.x; ahf[mt][1] = v1.x; ahf[mt][2] = v0.z; ahf[mt][3] = v1.z;
            alf[mt][0] = v0.y; alf[mt][1] = v1.y; alf[mt][2] = v0.w; alf[mt][3] = v1.w;
        }
#pragma unroll
        for (int nt = 0; nt < 4; nt++) {
            int col = wn * 32 + nt * 8 + g;
            uint2 w0 = *reinterpret_cast<const uint2*>(&Wsm[(kt * 8 + c) * WSTRIDE + col * 2]);
            uint2 w1 = *reinterpret_cast<const uint2*>(&Wsm[(kt * 8 + c + 4) * WSTRIDE + col * 2]);
#pragma unroll
            for (int mt = 0; mt < 4; mt++) {
                mma16816(acc[mt][nt], ahf[mt], w0.x, w1.x);
                mma16816(acc[mt][nt], ahf[mt], w0.y, w1.y);
                mma16816(acc[mt][nt], alf[mt], w0.x, w1.x);
            }
        }

        if (kt < 15) store_a(nxt);
        __syncthreads();
    }

    // ---- epilogue ----
#pragma unroll
    for (int mt = 0; mt < 4; mt++) {
        float ss0 = 0.0f, ss1 = 0.0f;
#pragma unroll
        for (int nt = 0; nt < 4; nt++) {
            int col = wn * 32 + nt * 8 + c * 2;
            float b0v = __ldg(cs.bb + col), b1v = __ldg(cs.bb + col + 1);
            acc[mt][nt][0] += b0v; acc[mt][nt][1] += b1v;
            acc[mt][nt][2] += b0v; acc[mt][nt][3] += b1v;
            ss0 += acc[mt][nt][0] * acc[mt][nt][0] + acc[mt][nt][1] * acc[mt][nt][1];
            ss1 += acc[mt][nt][2] * acc[mt][nt][2] + acc[mt][nt][3] * acc[mt][nt][3];
        }
        ss0 += __shfl_xor_sync(0xffffffffu, ss0, 1);
        ss0 += __shfl_xor_sync(0xffffffffu, ss0, 2);
        ss1 += __shfl_xor_sync(0xffffffffu, ss1, 1);
        ss1 += __shfl_xor_sync(0xffffffffu, ss1, 2);
        if (c == 0) {
            atomicAdd(&ssred[wm * 64 + mt * 16 + g],     ss0);
            atomicAdd(&ssred[wm * 64 + mt * 16 + 8 + g], ss1);
        }
    }
    __syncthreads();

#pragma unroll
    for (int mt = 0; mt < 4; mt++) {
        int rl0 = wm * 64 + mt * 16 + g;
        int rl1 = rl0 + 8;
        float inv0 = 1.0f / fmaxf(sqrtf(ssred[rl0]), 1e-12f);
        float inv1 = 1.0f / fmaxf(sqrtf(ssred[rl1]), 1e-12f);
        int gr0 = row0 + rl0;
        int gr1 = row0 + rl1;
#pragma unroll
        for (int nt = 0; nt < 4; nt++) {
            int col = wn * 32 + nt * 8 + c * 2;
            if (gr0 < n) {
                float v0 = acc[mt][nt][0] * inv0;
                float v1 = acc[mt][nt][1] * inv0;
                if (mode == 2) {
                    float2 a2 = *reinterpret_cast<const float2*>(cs.addin + (size_t)gr0 * H + col);
                    v0 += a2.x; v1 += a2.y;
                }
                if (mode >= 1) {
                    v0 = (v0 >= 0.f) ? v0 : 0.01f * v0;
                    v1 = (v1 >= 0.f) ? v1 : 0.01f * v1;
                }
                *reinterpret_cast<float2*>(cs.out + (size_t)gr0 * H + col) = make_float2(v0, v1);
            }
            if (gr1 < n) {
                float v2 = acc[mt][nt][2] * inv1;
                float v3 = acc[mt][nt][3] * inv1;
                if (mode == 2) {
                    float2 a2 = *reinterpret_cast<const float2*>(cs.addin + (size_t)gr1 * H + col);
                    v2 += a2.x; v3 += a2.y;
                }
                if (mode >= 1) {
                    v2 = (v2 >= 0.f) ? v2 : 0.01f * v2;
                    v3 = (v3 >= 0.f) ? v3 : 0.01f * v3;
                }
                *reinterpret_cast<float2*>(cs.out + (size_t)gr1 * H + col) = make_float2(v2, v3);
            }
        }
    }
}

// ---------------- host ----------------
extern "C" void kernel_launch(void* const* d_in, const int* in_sizes, int n_in,
                              void* d_out, int out_size)
{
    const float* x_ip  = (const float*)d_in[0];
    const float* x_con = (const float*)d_in[1];
    const int* src_ipcon = (const int*)d_in[2];
    const int* dst_ipcon = (const int*)d_in[3];
    const int* src_conip = (const int*)d_in[4];
    const int* dst_conip = (const int*)d_in[5];
    const int* src_ipip  = (const int*)d_in[6];
    const int* dst_ipip  = (const int*)d_in[7];
    const int* src_csrc  = (const int*)d_in[8];
    const int* dst_csrc  = (const int*)d_in[9];
    const int* src_cdst  = (const int*)d_in[10];
    const int* dst_cdst  = (const int*)d_in[11];
    const float* Wl_t = (const float*)d_in[12];
    const float* bl_t = (const float*)d_in[13];
    const float* Wr_t = (const float*)d_in[14];
    const float* Wl_s = (const float*)d_in[15];
    const float* bl_s = (const float*)d_in[16];
    const float* Wr_s = (const float*)d_in[17];

    const int n_ip  = in_sizes[0] / H;
    const int n_con = in_sizes[1] / H;
    const int nE_ipcon = in_sizes[2];
    const int nE_conip = in_sizes[4];
    const int nE_ipip  = in_sizes[6];
    const int nE_csrc  = in_sizes[8];
    const int nE_cdst  = in_sizes[10];

    float *s0, *s1, *s2, *ipA, *ipB, *conA, *conB;
    uint2* wsp;
    int *cnt, *off, *eidx, *part;
    cudaGetSymbolAddress((void**)&s0,   g_s0);
    cudaGetSymbolAddress((void**)&s1,   g_s1);
    cudaGetSymbolAddress((void**)&s2,   g_s2);
    cudaGetSymbolAddress((void**)&ipA,  g_ipA);
    cudaGetSymbolAddress((void**)&ipB,  g_ipB);
    cudaGetSymbolAddress((void**)&conA, g_conA);
    cudaGetSymbolAddress((void**)&conB, g_conB);
    cudaGetSymbolAddress((void**)&wsp,  g_wsplit);
    cudaGetSymbolAddress((void**)&cnt,  g_cnt);
    cudaGetSymbolAddress((void**)&off,  g_off);
    cudaGetSymbolAddress((void**)&eidx, g_eidx);
    cudaGetSymbolAddress((void**)&part, g_part);

    cudaFuncSetAttribute(combine_fused_kernel, cudaFuncAttributeMaxDynamicSharedMemorySize, DSMEM_BYTES);

    float* out = (float*)d_out;

    BuildParams bp;
    bp.e[0] = { src_ipip,  dst_ipip,  nE_ipip,  n_ip,  0,                0 };
    bp.e[1] = { src_csrc,  dst_csrc,  nE_csrc,  n_con, n_ip,             nE_ipip };
    bp.e[2] = { src_cdst,  dst_cdst,  nE_cdst,  n_con, n_ip + n_con,     nE_ipip + nE_csrc };
    bp.e[3] = { src_ipcon, dst_ipcon, nE_ipcon, n_con, n_ip + 2 * n_con, nE_ipip + nE_csrc + nE_cdst };
    bp.e[4] = { src_conip, dst_conip, nE_conip, n_ip,  n_ip + 3 * n_con, nE_ipip + nE_csrc + nE_cdst + nE_ipcon };

    int maxE = nE_ipip;
    if (nE_csrc  > maxE) maxE = nE_csrc;
    if (nE_cdst  > maxE) maxE = nE_cdst;
    if (nE_ipcon > maxE) maxE = nE_ipcon;
    if (nE_conip > maxE) maxE = nE_conip;
    const int cntBlocks = (maxE + 255) / 256;

    // launch 1: presplit + count (cnt starts all-zero; fill restores it)
    precount_kernel<<<640 + 5 * cntBlocks, 256>>>(Wl_t, Wr_t, Wl_s, Wr_s, wsp, bp, cnt, cntBlocks);
    // launches 2-4: scans + fill
    scan_phase1<<<dim3(MAXB, 5), 1024>>>(bp, cnt, off, part);
    scan_phase23<<<dim3(MAXB, 5), 1024>>>(bp, off, part);
    fill_kernel<<<dim3(cntBlocks, 5), 256>>>(bp, cnt, off, eidx);

    const int* off0 = off + bp.e[0].dstbase + 0;
    const int* off1 = off + bp.e[1].dstbase + 1;
    const int* off2 = off + bp.e[2].dstbase + 2;
    const int* off3 = off + bp.e[3].dstbase + 3;
    const int* off4 = off + bp.e[4].dstbase + 4;
    const int* ei0 = eidx + bp.e[0].ebase;
    const int* ei1 = eidx + bp.e[1].ebase;
    const int* ei2 = eidx + bp.e[2].ebase;
    const int* ei3 = eidx + bp.e[3].ebase;
    const int* ei4 = eidx + bp.e[4].ebase;

    const int nbIP  = (n_ip  + 255) / 256;
    const int nbCON = (n_con + 255) / 256;
    const int aggBlocksCon = (n_con * 32 + 255) / 256;
    const int aggBlocksIp  = (n_ip  * 32 + 255) / 256;
    const size_t WSZ = 16384;

    for (int l = 0; l < 2; l++) {
        const float* xi = (l == 0) ? x_ip  : ipB;
        const float* xc = (l == 0) ? x_con : conB;

        const float* b0 = bl_t + (size_t)(l * 3 + 0) * H;
        const float* b1 = bl_t + (size_t)(l * 3 + 1) * H;
        const float* b2 = bl_t + (size_t)(l * 3 + 2) * H;
        const float* bs0 = bl_s + (size_t)(l * 2 + 0) * H;
        const float* bs1 = bl_s + (size_t)(l * 2 + 1) * H;

        // ---------- temporal aggregation (3 segments, fused) ----------
        AggSeg a0 = { xi, off0, ei0, s0, n_ip };
        AggSeg a1 = { xc, off1, ei1, s1, n_con };
        AggSeg a2 = { xc, off2, ei2, s2, n_con };
        agg_fused_kernel<<<dim3(aggBlocksCon, 3), 256>>>(a0, a1, a2);

        // ---------- temporal combines: (ip sage + con sage1) fused, then con sage2 ----------
        CombSeg cIP  = { s0, xi, wsp + (size_t)(l * 3 + 0) * WSZ, b0, nullptr, ipA, n_ip,  nbIP,  1 };
        CombSeg cC1  = { s1, xc, wsp + (size_t)(l * 3 + 1) * WSZ, b1, nullptr, s1,  n_con, nbCON, 0 };
        combine_fused_kernel<<<nbIP + nbCON, 512, DSMEM_BYTES>>>(cIP, cC1);

        CombSeg cC2  = { s2, xc, wsp + (size_t)(l * 3 + 2) * WSZ, b2, s1, conA, n_con, nbCON, 2 };
        CombSeg cNil = { nullptr, nullptr, nullptr, nullptr, nullptr, nullptr, 0, 0, 0 };
        combine_fused_kernel<<<nbCON, 512, DSMEM_BYTES>>>(cC2, cNil);

        // ---------- spatial aggregation (2 segments, fused) ----------
        AggSeg a3 = { ipA,  off3, ei3, s1, n_con };
        AggSeg a4 = { conA, off4, ei4, s0, n_ip };
        agg_fused_kernel<<<dim3(aggBlocksCon, 2), 256>>>(a3, a4, a4);

        // ---------- spatial combines fused ----------
        float* out_ip  = (l == 1) ? out : ipB;
        float* out_con = (l == 1) ? (out + (size_t)n_ip * H) : conB;

        CombSeg cSC = { s1, conA, wsp + (size_t)(6 + l * 2 + 0) * WSZ, bs0, nullptr, out_con, n_con, nbCON, 1 };
        CombSeg cSI = { s0, ipA,  wsp + (size_t)(6 + l * 2 + 1) * WSZ, bs1, nullptr, out_ip,  n_ip,  nbIP,  1 };
        combine_fused_kernel<<<nbCON + nbIP, 512, DSMEM_BYTES>>>(cSC, cSI);
    }
    (void)aggBlocksIp;
}